// round 16
// baseline (speedup 1.0000x reference)
#include <cuda_runtime.h>
#include <cstdint>

#define S_LEN 2048
#define NHEAD 16
#define HDIM  64
#define DMODEL 1024
#define BATCH 2
#define NROWS (BATCH * S_LEN)          // 4096
#define NTILES 128                     // S_LEN / 16
#define OUT_ELEMS ((size_t)NROWS * DMODEL)                 // 4,194,304
#define IDX_ELEMS ((size_t)BATCH * NHEAD * S_LEN * 8)      // 524,288
#define FCN (S_LEN * 32)
#define KC_PANEL 512                   // Eigen gebp kc: 2 panels — FROZEN

// ---------------- scratch (static device globals; no allocation) -------------
__device__ float g_Q [BATCH * NHEAD * S_LEN * HDIM];   // [b,h,s,d]
__device__ float g_K [BATCH * NHEAD * S_LEN * HDIM];   // [b,h,s,d]
__device__ float g_V [NROWS * DMODEL];                 // [b,s,h*d]
__device__ float g_O [NROWS * DMODEL];                 // [b,s,h*d]
__device__ float g_TM[(size_t)BATCH * NHEAD * S_LEN * NTILES]; // tile max logits
__device__ float2 g_FC[FCN];                           // (cos, sin) table

// ---------------- RoPE table: numpy's f64 recipe (FROZEN) ---------------------
__global__ void fc_kernel()
{
    int idx = blockIdx.x * blockDim.x + threadIdx.x;
    if (idx >= FCN) return;
    int s = idx >> 5, j = idx & 31;
    double inv_freq = 1.0 / pow(10000.0, ((double)(2 * j)) / 64.0);
    double ang = (double)s * inv_freq;
    g_FC[idx] = make_float2((float)cos(ang), (float)sin(ang));
}

__device__ __forceinline__ unsigned f2tf32(float x)
{
    unsigned r;
    asm("cvt.rna.tf32.f32 %0, %1;" : "=r"(r) : "f"(x));
    return r;
}

#define MMA_TF32(c, a0, a1, a2, a3, b0, b1) \
    asm volatile("mma.sync.aligned.m16n8k8.row.col.f32.tf32.tf32.f32 " \
        "{%0,%1,%2,%3},{%4,%5,%6,%7},{%8,%9},{%0,%1,%2,%3};" \
        : "+f"(c[0]), "+f"(c[1]), "+f"(c[2]), "+f"(c[3]) \
        : "r"(a0), "r"(a1), "r"(a2), "r"(a3), "r"(b0), "r"(b1))

// =============================================================================
// Q & K projection GEMMs merged (grid.z selects), 2-panel kc=512 (FROZEN math),
// double-buffered smem. 128x128 tile, BK=8, 8x8 microtile; P0 spilled to smem.
// =============================================================================
__global__ __launch_bounds__(256, 2)
void sgemm_qk_panel(const float* __restrict__ A,
                    const float* __restrict__ Wq, const float* __restrict__ Wk,
                    float* __restrict__ Cq, float* __restrict__ Ck,
                    int N, int K)
{
    extern __shared__ float sm[];
    float* As    = sm;            // 2 x [8][128]
    float* Bs    = sm + 2048;     // 2 x [8][128]
    float* spill = sm + 4096;     // [256][64] committed P0

    const float* B = blockIdx.z ? Wk : Wq;
    float*       C = blockIdx.z ? Ck : Cq;

    const int tid  = threadIdx.x;
    const float* Ab = A + (size_t)blockIdx.y * 128 * K;
    const float* Bb = B + (size_t)blockIdx.x * 128;

    const int arow = tid >> 1;
    const int acol = (tid & 1) * 4;
    const int brw  = tid >> 5;
    const int bcl  = (tid & 31) * 4;
    const int tr = (tid >> 4) * 8;
    const int tc = (tid & 15) * 8;

    float acc[8][8];
    #pragma unroll
    for (int i = 0; i < 8; ++i)
        #pragma unroll
        for (int j = 0; j < 8; ++j) acc[i][j] = 0.f;

    {
        float4 av = *(const float4*)(Ab + (size_t)arow * K + acol);
        As[(acol + 0) * 128 + arow] = av.x;
        As[(acol + 1) * 128 + arow] = av.y;
        As[(acol + 2) * 128 + arow] = av.z;
        As[(acol + 3) * 128 + arow] = av.w;
        float4 bv = *(const float4*)(Bb + (size_t)brw * N + bcl);
        *(float4*)&Bs[brw * 128 + bcl] = bv;
    }
    __syncthreads();

    int buf = 0;
    for (int k0 = 0; k0 < K; k0 += 8) {
        float4 nav, nbv;
        const bool has = (k0 + 8 < K);
        if (has) {
            nav = *(const float4*)(Ab + (size_t)arow * K + k0 + 8 + acol);
            nbv = *(const float4*)(Bb + (size_t)(k0 + 8 + brw) * N + bcl);
        }

        const float* Ac = As + buf * 1024;
        const float* Bc = Bs + buf * 1024;
        #pragma unroll
        for (int kk = 0; kk < 8; ++kk) {   // ascending k, serial chain (FROZEN)
            float ra[8], rb[8];
            #pragma unroll
            for (int i = 0; i < 8; ++i) ra[i] = Ac[kk * 128 + tr + i];
            #pragma unroll
            for (int j = 0; j < 8; ++j) rb[j] = Bc[kk * 128 + tc + j];
            #pragma unroll
            for (int i = 0; i < 8; ++i)
                #pragma unroll
                for (int j = 0; j < 8; ++j)
                    acc[i][j] = fmaf(ra[i], rb[j], acc[i][j]);
        }

        if (k0 + 8 == KC_PANEL) {          // commit P0
            #pragma unroll
            for (int i = 0; i < 8; ++i)
                #pragma unroll
                for (int j = 0; j < 8; ++j) {
                    spill[tid * 64 + i * 8 + j] = acc[i][j];
                    acc[i][j] = 0.f;
                }
        }

        if (has) {
            float* An = As + (buf ^ 1) * 1024;
            float* Bn = Bs + (buf ^ 1) * 1024;
            An[(acol + 0) * 128 + arow] = nav.x;
            An[(acol + 1) * 128 + arow] = nav.y;
            An[(acol + 2) * 128 + arow] = nav.z;
            An[(acol + 3) * 128 + arow] = nav.w;
            *(float4*)&Bn[brw * 128 + bcl] = nbv;
        }
        __syncthreads();
        buf ^= 1;
    }

    const int rowbase = blockIdx.y * 128 + tr;
    const int d0 = tc & 63;
    const int colh = (blockIdx.x * 128 + tc) >> 6;  // global head index
    #pragma unroll
    for (int i = 0; i < 8; ++i) {
        int row = rowbase + i;
        int b = row >> 11, s = row & (S_LEN - 1);
        float res[8];
        #pragma unroll
        for (int j = 0; j < 8; ++j)
            res[j] = __fadd_rn(spill[tid * 64 + i * 8 + j], acc[i][j]); // P0+P1
        float* cp = C + (((size_t)b * NHEAD + colh) * S_LEN + s) * HDIM + d0;
        *(float4*)(cp)     = make_float4(res[0], res[1], res[2], res[3]);
        *(float4*)(cp + 4) = make_float4(res[4], res[5], res[6], res[7]);
    }
}

// =============================================================================
// tf32 tensor-core GEMM for V projection and O projection (out0-only)
// =============================================================================
__global__ __launch_bounds__(256, 2)
void sgemm_tf32(const float* __restrict__ A, const float* __restrict__ B,
                float* __restrict__ C, int N, int K)
{
    __shared__ unsigned As[2][16][136];
    __shared__ unsigned Bs[2][16][136];

    const int tid  = threadIdx.x;
    const int lane = tid & 31;
    const int wid  = tid >> 5;
    const int wm   = (wid >> 2) * 64;
    const int wn   = (wid & 3) * 32;

    const float* Ab = A + (size_t)blockIdx.y * 128 * K;
    const float* Bb = B + (size_t)blockIdx.x * 128;

    const int ar = tid >> 1;
    const int ak = (tid & 1) * 8;
    const int bk = tid >> 4;
    const int bn = (tid & 15) * 8;

    float c[4][4][4];
    #pragma unroll
    for (int mt = 0; mt < 4; ++mt)
        #pragma unroll
        for (int nt = 0; nt < 4; ++nt)
            #pragma unroll
            for (int e = 0; e < 4; ++e) c[mt][nt][e] = 0.f;

    {
        float4 a0 = *(const float4*)(Ab + (size_t)ar * K + ak);
        float4 a1 = *(const float4*)(Ab + (size_t)ar * K + ak + 4);
        As[0][ak + 0][ar] = f2tf32(a0.x);  As[0][ak + 1][ar] = f2tf32(a0.y);
        As[0][ak + 2][ar] = f2tf32(a0.z);  As[0][ak + 3][ar] = f2tf32(a0.w);
        As[0][ak + 4][ar] = f2tf32(a1.x);  As[0][ak + 5][ar] = f2tf32(a1.y);
        As[0][ak + 6][ar] = f2tf32(a1.z);  As[0][ak + 7][ar] = f2tf32(a1.w);
        float4 b0 = *(const float4*)(Bb + (size_t)bk * N + bn);
        float4 b1 = *(const float4*)(Bb + (size_t)bk * N + bn + 4);
        Bs[0][bk][bn + 0] = f2tf32(b0.x);  Bs[0][bk][bn + 1] = f2tf32(b0.y);
        Bs[0][bk][bn + 2] = f2tf32(b0.z);  Bs[0][bk][bn + 3] = f2tf32(b0.w);
        Bs[0][bk][bn + 4] = f2tf32(b1.x);  Bs[0][bk][bn + 5] = f2tf32(b1.y);
        Bs[0][bk][bn + 6] = f2tf32(b1.z);  Bs[0][bk][bn + 7] = f2tf32(b1.w);
    }
    __syncthreads();

    int buf = 0;
    for (int k0 = 0; k0 < K; k0 += 16) {
        float4 pa0, pa1, pb0, pb1;
        const bool has = (k0 + 16 < K);
        if (has) {
            pa0 = *(const float4*)(Ab + (size_t)ar * K + k0 + 16 + ak);
            pa1 = *(const float4*)(Ab + (size_t)ar * K + k0 + 16 + ak + 4);
            pb0 = *(const float4*)(Bb + (size_t)(k0 + 16 + bk) * N + bn);
            pb1 = *(const float4*)(Bb + (size_t)(k0 + 16 + bk) * N + bn + 4);
        }

        #pragma unroll
        for (int k8 = 0; k8 < 2; ++k8) {
            const int klo = k8 * 8 + (lane & 3);
            const int khi = klo + 4;
            unsigned b[4][2];
            #pragma unroll
            for (int nt = 0; nt < 4; ++nt) {
                int n = wn + nt * 8 + (lane >> 2);
                b[nt][0] = Bs[buf][klo][n];
                b[nt][1] = Bs[buf][khi][n];
            }
            #pragma unroll
            for (int mt = 0; mt < 4; ++mt) {
                int m = wm + mt * 16 + (lane >> 2);
                unsigned a0 = As[buf][klo][m];
                unsigned a1 = As[buf][klo][m + 8];
                unsigned a2 = As[buf][khi][m];
                unsigned a3 = As[buf][khi][m + 8];
                #pragma unroll
                for (int nt = 0; nt < 4; ++nt)
                    MMA_TF32(c[mt][nt], a0, a1, a2, a3, b[nt][0], b[nt][1]);
            }
        }

        if (has) {
            int nb = buf ^ 1;
            As[nb][ak + 0][ar] = f2tf32(pa0.x);  As[nb][ak + 1][ar] = f2tf32(pa0.y);
            As[nb][ak + 2][ar] = f2tf32(pa0.z);  As[nb][ak + 3][ar] = f2tf32(pa0.w);
            As[nb][ak + 4][ar] = f2tf32(pa1.x);  As[nb][ak + 5][ar] = f2tf32(pa1.y);
            As[nb][ak + 6][ar] = f2tf32(pa1.z);  As[nb][ak + 7][ar] = f2tf32(pa1.w);
            Bs[nb][bk][bn + 0] = f2tf32(pb0.x);  Bs[nb][bk][bn + 1] = f2tf32(pb0.y);
            Bs[nb][bk][bn + 2] = f2tf32(pb0.z);  Bs[nb][bk][bn + 3] = f2tf32(pb0.w);
            Bs[nb][bk][bn + 4] = f2tf32(pb1.x);  Bs[nb][bk][bn + 5] = f2tf32(pb1.y);
            Bs[nb][bk][bn + 6] = f2tf32(pb1.z);  Bs[nb][bk][bn + 7] = f2tf32(pb1.w);
        }
        __syncthreads();
        buf ^= 1;
    }

    const int rowbase = blockIdx.y * 128;
    const int colbase = blockIdx.x * 128;
    #pragma unroll
    for (int mt = 0; mt < 4; ++mt) {
        int r = rowbase + wm + mt * 16 + (lane >> 2);
        #pragma unroll
        for (int nt = 0; nt < 4; ++nt) {
            int cc = colbase + wn + nt * 8 + (lane & 3) * 2;
            *(float2*)(C + (size_t)r * N + cc)       = make_float2(c[mt][nt][0], c[mt][nt][1]);
            *(float2*)(C + (size_t)(r + 8) * N + cc) = make_float2(c[mt][nt][2], c[mt][nt][3]);
        }
    }
}

// ---------------- RoPE: FROZEN form  fma(x, cos, fl(rot*sin)) ----------------
__global__ void rope_kernel()
{
    int idx = blockIdx.x * blockDim.x + threadIdx.x;   // 1<<22 threads
    int j  = idx & 31;
    int s  = (idx >> 5) & (S_LEN - 1);
    int bh = (idx >> 16) & 31;
    float* buf = (idx >> 21) ? g_K : g_Q;
    float2 cs = g_FC[s * 32 + j];
    float* p = buf + ((size_t)bh * S_LEN + s) * HDIM;
    float x0 = p[j], x1 = p[j + 32];
    p[j]      = __fmaf_rn(x0, cs.x, -__fmul_rn(x1, cs.y));
    p[j + 32] = __fmaf_rn(x1, cs.x,  __fmul_rn(x0, cs.y));
}

// ---------------- flash attention: FROZEN QK/softmax + tf32 PV ---------------
// 128 threads. K/V register-prefetch double buffering (values unchanged).
__global__ __launch_bounds__(128, 3)
void attn_kernel()
{
    extern __shared__ float smem[];
    float*    Qs = smem;                             // [64][68] fp32
    float*    Ks = smem + 64 * 68;                   // [64][68] fp32
    unsigned* Vs = (unsigned*)(smem + 2 * 64 * 68);  // [64][68] tf32 bits
    unsigned* Ps = (unsigned*)(smem + 3 * 64 * 68);  // [64][68] tf32 bits
    float* alpha_s = smem + 4 * 64 * 68;             // [64]
    float* l_s     = smem + 4 * 64 * 68 + 64;        // [64]

    const int bh = blockIdx.y;
    const int q0 = (gridDim.x - 1 - blockIdx.x) * 64;   // longest first
    const int b  = bh >> 4, h = bh & 15;
    const float* Qp = g_Q + (size_t)bh * S_LEN * HDIM;
    const float* Kp = g_K + (size_t)bh * S_LEN * HDIM;
    const float* Vp = g_V + (size_t)b * S_LEN * DMODEL + h * HDIM;

    const int tid  = threadIdx.x;
    const int lane = tid & 31;
    const int wid  = tid >> 5;
    const int ty = tid >> 4, tx = tid & 15;
    const int r0 = ty * 8, c0 = tx * 4;
    const unsigned FULL = 0xffffffffu;

    const int lrow0 = tid >> 4;          // 0..7
    const int lc4   = (tid & 15) * 4;

    for (int it = tid; it < 64 * 16; it += 128) {
        int row = it >> 4, c4 = (it & 15) * 4;
        *(float4*)&Qs[row * 68 + c4] = *(const float4*)(Qp + (size_t)(q0 + row) * HDIM + c4);
    }

    float m[8], l[8];
    #pragma unroll
    for (int i = 0; i < 8; ++i) { m[i] = -1e30f; l[i] = 0.f; }

    float c[8][4];
    #pragma unroll
    for (int nf = 0; nf < 8; ++nf)
        #pragma unroll
        for (int e = 0; e < 4; ++e) c[nf][e] = 0.f;
    const int frow = wid * 16 + (lane >> 2);

    // prefetch kt = 0
    float4 kr[8], vr[8];
    #pragma unroll
    for (int u = 0; u < 8; ++u) {
        int row = lrow0 + u * 8;
        kr[u] = *(const float4*)(Kp + (size_t)row * HDIM + lc4);
        vr[u] = *(const float4*)(Vp + (size_t)row * DMODEL + lc4);
    }

    const int ktmax = (q0 + 63) >> 6;
    for (int kt = 0; kt <= ktmax; ++kt) {
        __syncthreads();                 // prev PV done reading Vs/Ps
        #pragma unroll
        for (int u = 0; u < 8; ++u) {
            int row = lrow0 + u * 8;
            *(float4*)&Ks[row * 68 + lc4] = kr[u];
            Vs[row * 68 + lc4 + 0] = f2tf32(vr[u].x);
            Vs[row * 68 + lc4 + 1] = f2tf32(vr[u].y);
            Vs[row * 68 + lc4 + 2] = f2tf32(vr[u].z);
            Vs[row * 68 + lc4 + 3] = f2tf32(vr[u].w);
        }
        __syncthreads();

        if (kt < ktmax) {                // prefetch next tile (latency hidden)
            const int kn = (kt + 1) * 64;
            #pragma unroll
            for (int u = 0; u < 8; ++u) {
                int row = kn + lrow0 + u * 8;
                kr[u] = *(const float4*)(Kp + (size_t)row * HDIM + lc4);
                vr[u] = *(const float4*)(Vp + (size_t)row * DMODEL + lc4);
            }
        }

        const int k0 = kt * 64;

        // QK^T: serial ascending-d fmaf chain (bitwise FROZEN)
        float s[8][4];
        #pragma unroll
        for (int i = 0; i < 8; ++i)
            #pragma unroll
            for (int j = 0; j < 4; ++j) s[i][j] = 0.f;

        #pragma unroll 4
        for (int d4 = 0; d4 < 16; ++d4) {
            float4 rk[4];
            #pragma unroll
            for (int j = 0; j < 4; ++j) rk[j] = *(float4*)&Ks[(c0 + j) * 68 + d4 * 4];
            #pragma unroll
            for (int i = 0; i < 8; ++i) {
                float4 rq = *(float4*)&Qs[(r0 + i) * 68 + d4 * 4];
                #pragma unroll
                for (int j = 0; j < 4; ++j) {
                    s[i][j] = fmaf(rq.x, rk[j].x, s[i][j]);
                    s[i][j] = fmaf(rq.y, rk[j].y, s[i][j]);
                    s[i][j] = fmaf(rq.z, rk[j].z, s[i][j]);
                    s[i][j] = fmaf(rq.w, rk[j].w, s[i][j]);
                }
            }
        }

        // scale (exact /8) + causal mask (FROZEN)
        #pragma unroll
        for (int i = 0; i < 8; ++i) {
            int qi = q0 + r0 + i;
            #pragma unroll
            for (int j = 0; j < 4; ++j) {
                int kj = k0 + c0 + j;
                s[i][j] = (kj <= qi) ? s[i][j] * 0.125f : -1e10f;
            }
        }

        // per-row online softmax + tile-max recording (FROZEN)
        #pragma unroll
        for (int i = 0; i < 8; ++i) {
            float tmax = fmaxf(fmaxf(s[i][0], s[i][1]), fmaxf(s[i][2], s[i][3]));
            tmax = fmaxf(tmax, __shfl_xor_sync(FULL, tmax, 1));
            tmax = fmaxf(tmax, __shfl_xor_sync(FULL, tmax, 2));
            if ((tx & 3) == 0) {
                int tile = kt * 4 + (tx >> 2);
                int qi = q0 + r0 + i;
                g_TM[((size_t)bh * S_LEN + qi) * NTILES + tile] = tmax;
            }
            float rmax = fmaxf(tmax, __shfl_xor_sync(FULL, tmax, 4));
            rmax = fmaxf(rmax, __shfl_xor_sync(FULL, rmax, 8));

            float mnew  = fmaxf(m[i], rmax);
            float alpha = __expf(m[i] - mnew);
            m[i] = mnew;

            float psum = 0.f;
            #pragma unroll
            for (int j = 0; j < 4; ++j) {
                float p = __expf(s[i][j] - mnew);
                s[i][j] = p;
                psum += p;
            }
            psum += __shfl_xor_sync(FULL, psum, 1);
            psum += __shfl_xor_sync(FULL, psum, 2);
            psum += __shfl_xor_sync(FULL, psum, 4);
            psum += __shfl_xor_sync(FULL, psum, 8);
            l[i] = l[i] * alpha + psum;

            if (tx == 0) alpha_s[r0 + i] = alpha;
            #pragma unroll
            for (int j = 0; j < 4; ++j)
                Ps[(r0 + i) * 68 + c0 + j] = f2tf32(s[i][j]);
        }
        __syncthreads();

        // PV via tf32 mma: O_frag = alpha * O_frag + P @ V
        float a_lo = alpha_s[frow];
        float a_hi = alpha_s[frow + 8];
        #pragma unroll
        for (int nf = 0; nf < 8; ++nf) {
            c[nf][0] *= a_lo; c[nf][1] *= a_lo;
            c[nf][2] *= a_hi; c[nf][3] *= a_hi;
        }
        #pragma unroll
        for (int kb = 0; kb < 8; ++kb) {
            int klo = kb * 8 + (lane & 3);
            int khi = klo + 4;
            unsigned a0 = Ps[frow * 68 + klo];
            unsigned a1 = Ps[(frow + 8) * 68 + klo];
            unsigned a2 = Ps[frow * 68 + khi];
            unsigned a3 = Ps[(frow + 8) * 68 + khi];
            #pragma unroll
            for (int nf = 0; nf < 8; ++nf) {
                unsigned b0 = Vs[klo * 68 + nf * 8 + (lane >> 2)];
                unsigned b1 = Vs[khi * 68 + nf * 8 + (lane >> 2)];
                MMA_TF32(c[nf], a0, a1, a2, a3, b0, b1);
            }
        }
    }

    if (tx == 0) {
        #pragma unroll
        for (int i = 0; i < 8; ++i) l_s[r0 + i] = l[i];
    }
    __syncthreads();

    {
        float inv_lo = 1.0f / l_s[frow];
        float inv_hi = 1.0f / l_s[frow + 8];
        int q_lo = q0 + frow, q_hi = q0 + frow + 8;
        float* op_lo = g_O + ((size_t)b * S_LEN + q_lo) * DMODEL + h * HDIM;
        float* op_hi = g_O + ((size_t)b * S_LEN + q_hi) * DMODEL + h * HDIM;
        #pragma unroll
        for (int nf = 0; nf < 8; ++nf) {
            int d = nf * 8 + (lane & 3) * 2;
            *(float2*)(op_lo + d) = make_float2(c[nf][0] * inv_lo, c[nf][1] * inv_lo);
            *(float2*)(op_hi + d) = make_float2(c[nf][2] * inv_hi, c[nf][3] * inv_hi);
        }
    }
}

// ---------------- top-8 tile selection by logit (one warp per query row) -----
__global__ void topk_kernel(float* __restrict__ oidx)
{
    int gw   = (blockIdx.x * blockDim.x + threadIdx.x) >> 5;
    int lane = threadIdx.x & 31;
    int q = gw & (S_LEN - 1);
    int qtile = q >> 4;
    const float* tm = g_TM + (size_t)gw * NTILES;

    float v[4];
    #pragma unroll
    for (int u = 0; u < 4; ++u) {
        int t = lane + u * 32;
        v[u] = (t <= qtile) ? tm[t] : -1e10f;
    }

    float* o = oidx + (size_t)gw * 8;
    for (int sel = 0; sel < 8; ++sel) {
        float bv = v[0]; int bi = lane;
        #pragma unroll
        for (int u = 1; u < 4; ++u) {
            int t = lane + u * 32;
            if (v[u] > bv) { bv = v[u]; bi = t; }
        }
        #pragma unroll
        for (int off = 16; off > 0; off >>= 1) {
            float ov = __shfl_xor_sync(0xffffffffu, bv, off);
            int   oi = __shfl_xor_sync(0xffffffffu, bi, off);
            if (ov > bv || (ov == bv && oi < bi)) { bv = ov; bi = oi; }
        }
        if (lane == 0) o[sel] = (float)bi;
        if ((bi & 31) == lane) v[bi >> 5] = -3.0e38f;
    }
}

// ---------------- launch ------------------------------------------------------
extern "C" void kernel_launch(void* const* d_in, const int* in_sizes, int n_in,
                              void* d_out, int out_size)
{
    const float*  x  = (const float*)d_in[0];
    const float*  wq = (const float*)d_in[1];
    const float*  wk = (const float*)d_in[2];
    const float*  wv = (const float*)d_in[3];
    const float*  wo = (const float*)d_in[4];
    float* out = (float*)d_out;

    float *qb, *kb, *vb, *ob;
    cudaGetSymbolAddress((void**)&qb,  g_Q);
    cudaGetSymbolAddress((void**)&kb,  g_K);
    cudaGetSymbolAddress((void**)&vb,  g_V);
    cudaGetSymbolAddress((void**)&ob,  g_O);

    fc_kernel<<<(FCN + 255) / 256, 256>>>();

    // Q & K projections in one launch (grid.z selects weight/output)
    int qk_smem = (4096 + 256 * 64) * (int)sizeof(float);   // 81920 B
    cudaFuncSetAttribute(sgemm_qk_panel, cudaFuncAttributeMaxDynamicSharedMemorySize, qk_smem);
    dim3 qk_grid(DMODEL / 128, NROWS / 128, 2);
    sgemm_qk_panel<<<qk_grid, 256, qk_smem>>>(x, wq, wk, qb, kb, DMODEL, DMODEL);

    // V projection: tf32 tensor cores (out0-only)
    dim3 gemm_grid(DMODEL / 128, NROWS / 128);
    sgemm_tf32<<<gemm_grid, 256>>>(x, wv, vb, DMODEL, DMODEL);

    rope_kernel<<<(1 << 22) / 256, 256>>>();

    int smem_bytes = (4 * 64 * 68 + 128) * (int)sizeof(float);  // 70144 B
    cudaFuncSetAttribute(attn_kernel, cudaFuncAttributeMaxDynamicSharedMemorySize, smem_bytes);
    attn_kernel<<<dim3(S_LEN / 64, BATCH * NHEAD), 128, smem_bytes>>>();

    // O projection: tf32 tensor cores (out0-only)
    sgemm_tf32<<<gemm_grid, 256>>>(ob, wo, out, DMODEL, DMODEL);

    if ((size_t)out_size >= OUT_ELEMS + IDX_ELEMS) {
        topk_kernel<<<(BATCH * NHEAD * S_LEN * 32) / 256, 256>>>(out + OUT_ELEMS);
    }
}

// round 17
// speedup vs baseline: 1.0716x; 1.0716x over previous
#include <cuda_runtime.h>
#include <cstdint>

#define S_LEN 2048
#define NHEAD 16
#define HDIM  64
#define DMODEL 1024
#define BATCH 2
#define NROWS (BATCH * S_LEN)          // 4096
#define NTILES 128                     // S_LEN / 16
#define OUT_ELEMS ((size_t)NROWS * DMODEL)                 // 4,194,304
#define IDX_ELEMS ((size_t)BATCH * NHEAD * S_LEN * 8)      // 524,288
#define FCN (S_LEN * 32)
#define KC_PANEL 512                   // Eigen gebp kc: 2 panels — FROZEN

// ---------------- scratch (static device globals; no allocation) -------------
__device__ float g_Q [BATCH * NHEAD * S_LEN * HDIM];   // [b,h,s,d]
__device__ float g_K [BATCH * NHEAD * S_LEN * HDIM];   // [b,h,s,d]
__device__ float g_V [NROWS * DMODEL];                 // [b,s,h*d]
__device__ float g_O [NROWS * DMODEL];                 // [b,s,h*d]
__device__ float g_TM[(size_t)BATCH * NHEAD * S_LEN * NTILES]; // tile max logits
__device__ float2 g_FC[FCN];                           // (cos, sin) table

// ---------------- RoPE table: numpy's f64 recipe (FROZEN) ---------------------
__global__ void fc_kernel()
{
    int idx = blockIdx.x * blockDim.x + threadIdx.x;
    if (idx >= FCN) return;
    int s = idx >> 5, j = idx & 31;
    double inv_freq = 1.0 / pow(10000.0, ((double)(2 * j)) / 64.0);
    double ang = (double)s * inv_freq;
    g_FC[idx] = make_float2((float)cos(ang), (float)sin(ang));
}

__device__ __forceinline__ unsigned f2tf32(float x)
{
    unsigned r;
    asm("cvt.rna.tf32.f32 %0, %1;" : "=r"(r) : "f"(x));
    return r;
}

#define MMA_TF32(c, a0, a1, a2, a3, b0, b1) \
    asm volatile("mma.sync.aligned.m16n8k8.row.col.f32.tf32.tf32.f32 " \
        "{%0,%1,%2,%3},{%4,%5,%6,%7},{%8,%9},{%0,%1,%2,%3};" \
        : "+f"(c[0]), "+f"(c[1]), "+f"(c[2]), "+f"(c[3]) \
        : "r"(a0), "r"(a1), "r"(a2), "r"(a3), "r"(b0), "r"(b1))

// =============================================================================
// Q & K projection GEMMs merged (grid.z selects), 2-panel kc=512 (FROZEN math),
// double-buffered smem. 128x128 tile, BK=8, 8x8 microtile; P0 spilled to smem.
// =============================================================================
__global__ __launch_bounds__(256, 2)
void sgemm_qk_panel(const float* __restrict__ A,
                    const float* __restrict__ Wq, const float* __restrict__ Wk,
                    float* __restrict__ Cq, float* __restrict__ Ck,
                    int N, int K)
{
    extern __shared__ float sm[];
    float* As    = sm;            // 2 x [8][128]
    float* Bs    = sm + 2048;     // 2 x [8][128]
    float* spill = sm + 4096;     // [256][64] committed P0

    const float* B = blockIdx.z ? Wk : Wq;
    float*       C = blockIdx.z ? Ck : Cq;

    const int tid  = threadIdx.x;
    const float* Ab = A + (size_t)blockIdx.y * 128 * K;
    const float* Bb = B + (size_t)blockIdx.x * 128;

    const int arow = tid >> 1;
    const int acol = (tid & 1) * 4;
    const int brw  = tid >> 5;
    const int bcl  = (tid & 31) * 4;
    const int tr = (tid >> 4) * 8;
    const int tc = (tid & 15) * 8;

    float acc[8][8];
    #pragma unroll
    for (int i = 0; i < 8; ++i)
        #pragma unroll
        for (int j = 0; j < 8; ++j) acc[i][j] = 0.f;

    {
        float4 av = *(const float4*)(Ab + (size_t)arow * K + acol);
        As[(acol + 0) * 128 + arow] = av.x;
        As[(acol + 1) * 128 + arow] = av.y;
        As[(acol + 2) * 128 + arow] = av.z;
        As[(acol + 3) * 128 + arow] = av.w;
        float4 bv = *(const float4*)(Bb + (size_t)brw * N + bcl);
        *(float4*)&Bs[brw * 128 + bcl] = bv;
    }
    __syncthreads();

    int buf = 0;
    for (int k0 = 0; k0 < K; k0 += 8) {
        float4 nav, nbv;
        const bool has = (k0 + 8 < K);
        if (has) {
            nav = *(const float4*)(Ab + (size_t)arow * K + k0 + 8 + acol);
            nbv = *(const float4*)(Bb + (size_t)(k0 + 8 + brw) * N + bcl);
        }

        const float* Ac = As + buf * 1024;
        const float* Bc = Bs + buf * 1024;
        #pragma unroll
        for (int kk = 0; kk < 8; ++kk) {   // ascending k, serial chain (FROZEN)
            float ra[8], rb[8];
            #pragma unroll
            for (int i = 0; i < 8; ++i) ra[i] = Ac[kk * 128 + tr + i];
            #pragma unroll
            for (int j = 0; j < 8; ++j) rb[j] = Bc[kk * 128 + tc + j];
            #pragma unroll
            for (int i = 0; i < 8; ++i)
                #pragma unroll
                for (int j = 0; j < 8; ++j)
                    acc[i][j] = fmaf(ra[i], rb[j], acc[i][j]);
        }

        if (k0 + 8 == KC_PANEL) {          // commit P0
            #pragma unroll
            for (int i = 0; i < 8; ++i)
                #pragma unroll
                for (int j = 0; j < 8; ++j) {
                    spill[tid * 64 + i * 8 + j] = acc[i][j];
                    acc[i][j] = 0.f;
                }
        }

        if (has) {
            float* An = As + (buf ^ 1) * 1024;
            float* Bn = Bs + (buf ^ 1) * 1024;
            An[(acol + 0) * 128 + arow] = nav.x;
            An[(acol + 1) * 128 + arow] = nav.y;
            An[(acol + 2) * 128 + arow] = nav.z;
            An[(acol + 3) * 128 + arow] = nav.w;
            *(float4*)&Bn[brw * 128 + bcl] = nbv;
        }
        __syncthreads();
        buf ^= 1;
    }

    const int rowbase = blockIdx.y * 128 + tr;
    const int d0 = tc & 63;
    const int colh = (blockIdx.x * 128 + tc) >> 6;  // global head index
    #pragma unroll
    for (int i = 0; i < 8; ++i) {
        int row = rowbase + i;
        int b = row >> 11, s = row & (S_LEN - 1);
        float res[8];
        #pragma unroll
        for (int j = 0; j < 8; ++j)
            res[j] = __fadd_rn(spill[tid * 64 + i * 8 + j], acc[i][j]); // P0+P1
        float* cp = C + (((size_t)b * NHEAD + colh) * S_LEN + s) * HDIM + d0;
        *(float4*)(cp)     = make_float4(res[0], res[1], res[2], res[3]);
        *(float4*)(cp + 4) = make_float4(res[4], res[5], res[6], res[7]);
    }
}

// =============================================================================
// tf32 tensor-core GEMM for V projection and O projection (out0-only)
// =============================================================================
__global__ __launch_bounds__(256, 2)
void sgemm_tf32(const float* __restrict__ A, const float* __restrict__ B,
                float* __restrict__ C, int N, int K)
{
    __shared__ unsigned As[2][16][136];
    __shared__ unsigned Bs[2][16][136];

    const int tid  = threadIdx.x;
    const int lane = tid & 31;
    const int wid  = tid >> 5;
    const int wm   = (wid >> 2) * 64;
    const int wn   = (wid & 3) * 32;

    const float* Ab = A + (size_t)blockIdx.y * 128 * K;
    const float* Bb = B + (size_t)blockIdx.x * 128;

    const int ar = tid >> 1;
    const int ak = (tid & 1) * 8;
    const int bk = tid >> 4;
    const int bn = (tid & 15) * 8;

    float c[4][4][4];
    #pragma unroll
    for (int mt = 0; mt < 4; ++mt)
        #pragma unroll
        for (int nt = 0; nt < 4; ++nt)
            #pragma unroll
            for (int e = 0; e < 4; ++e) c[mt][nt][e] = 0.f;

    {
        float4 a0 = *(const float4*)(Ab + (size_t)ar * K + ak);
        float4 a1 = *(const float4*)(Ab + (size_t)ar * K + ak + 4);
        As[0][ak + 0][ar] = f2tf32(a0.x);  As[0][ak + 1][ar] = f2tf32(a0.y);
        As[0][ak + 2][ar] = f2tf32(a0.z);  As[0][ak + 3][ar] = f2tf32(a0.w);
        As[0][ak + 4][ar] = f2tf32(a1.x);  As[0][ak + 5][ar] = f2tf32(a1.y);
        As[0][ak + 6][ar] = f2tf32(a1.z);  As[0][ak + 7][ar] = f2tf32(a1.w);
        float4 b0 = *(const float4*)(Bb + (size_t)bk * N + bn);
        float4 b1 = *(const float4*)(Bb + (size_t)bk * N + bn + 4);
        Bs[0][bk][bn + 0] = f2tf32(b0.x);  Bs[0][bk][bn + 1] = f2tf32(b0.y);
        Bs[0][bk][bn + 2] = f2tf32(b0.z);  Bs[0][bk][bn + 3] = f2tf32(b0.w);
        Bs[0][bk][bn + 4] = f2tf32(b1.x);  Bs[0][bk][bn + 5] = f2tf32(b1.y);
        Bs[0][bk][bn + 6] = f2tf32(b1.z);  Bs[0][bk][bn + 7] = f2tf32(b1.w);
    }
    __syncthreads();

    int buf = 0;
    for (int k0 = 0; k0 < K; k0 += 16) {
        float4 pa0, pa1, pb0, pb1;
        const bool has = (k0 + 16 < K);
        if (has) {
            pa0 = *(const float4*)(Ab + (size_t)ar * K + k0 + 16 + ak);
            pa1 = *(const float4*)(Ab + (size_t)ar * K + k0 + 16 + ak + 4);
            pb0 = *(const float4*)(Bb + (size_t)(k0 + 16 + bk) * N + bn);
            pb1 = *(const float4*)(Bb + (size_t)(k0 + 16 + bk) * N + bn + 4);
        }

        #pragma unroll
        for (int k8 = 0; k8 < 2; ++k8) {
            const int klo = k8 * 8 + (lane & 3);
            const int khi = klo + 4;
            unsigned b[4][2];
            #pragma unroll
            for (int nt = 0; nt < 4; ++nt) {
                int n = wn + nt * 8 + (lane >> 2);
                b[nt][0] = Bs[buf][klo][n];
                b[nt][1] = Bs[buf][khi][n];
            }
            #pragma unroll
            for (int mt = 0; mt < 4; ++mt) {
                int m = wm + mt * 16 + (lane >> 2);
                unsigned a0 = As[buf][klo][m];
                unsigned a1 = As[buf][klo][m + 8];
                unsigned a2 = As[buf][khi][m];
                unsigned a3 = As[buf][khi][m + 8];
                #pragma unroll
                for (int nt = 0; nt < 4; ++nt)
                    MMA_TF32(c[mt][nt], a0, a1, a2, a3, b[nt][0], b[nt][1]);
            }
        }

        if (has) {
            int nb = buf ^ 1;
            As[nb][ak + 0][ar] = f2tf32(pa0.x);  As[nb][ak + 1][ar] = f2tf32(pa0.y);
            As[nb][ak + 2][ar] = f2tf32(pa0.z);  As[nb][ak + 3][ar] = f2tf32(pa0.w);
            As[nb][ak + 4][ar] = f2tf32(pa1.x);  As[nb][ak + 5][ar] = f2tf32(pa1.y);
            As[nb][ak + 6][ar] = f2tf32(pa1.z);  As[nb][ak + 7][ar] = f2tf32(pa1.w);
            Bs[nb][bk][bn + 0] = f2tf32(pb0.x);  Bs[nb][bk][bn + 1] = f2tf32(pb0.y);
            Bs[nb][bk][bn + 2] = f2tf32(pb0.z);  Bs[nb][bk][bn + 3] = f2tf32(pb0.w);
            Bs[nb][bk][bn + 4] = f2tf32(pb1.x);  Bs[nb][bk][bn + 5] = f2tf32(pb1.y);
            Bs[nb][bk][bn + 6] = f2tf32(pb1.z);  Bs[nb][bk][bn + 7] = f2tf32(pb1.w);
        }
        __syncthreads();
        buf ^= 1;
    }

    const int rowbase = blockIdx.y * 128;
    const int colbase = blockIdx.x * 128;
    #pragma unroll
    for (int mt = 0; mt < 4; ++mt) {
        int r = rowbase + wm + mt * 16 + (lane >> 2);
        #pragma unroll
        for (int nt = 0; nt < 4; ++nt) {
            int cc = colbase + wn + nt * 8 + (lane & 3) * 2;
            *(float2*)(C + (size_t)r * N + cc)       = make_float2(c[mt][nt][0], c[mt][nt][1]);
            *(float2*)(C + (size_t)(r + 8) * N + cc) = make_float2(c[mt][nt][2], c[mt][nt][3]);
        }
    }
}

// ---------------- RoPE: FROZEN form  fma(x, cos, fl(rot*sin)) ----------------
__global__ void rope_kernel()
{
    int idx = blockIdx.x * blockDim.x + threadIdx.x;   // 1<<22 threads
    int j  = idx & 31;
    int s  = (idx >> 5) & (S_LEN - 1);
    int bh = (idx >> 16) & 31;
    float* buf = (idx >> 21) ? g_K : g_Q;
    float2 cs = g_FC[s * 32 + j];
    float* p = buf + ((size_t)bh * S_LEN + s) * HDIM;
    float x0 = p[j], x1 = p[j + 32];
    p[j]      = __fmaf_rn(x0, cs.x, -__fmul_rn(x1, cs.y));
    p[j + 32] = __fmaf_rn(x1, cs.x,  __fmul_rn(x0, cs.y));
}

// ---------------- flash attention: FROZEN QK/softmax + tf32 tensor-core PV ---
// 128 threads (4 warps). QK: 8x4 microtile serial chain. PV: m16n8k8 fragments.
// (R15 proven body — no register prefetch)
__global__ __launch_bounds__(128, 3)
void attn_kernel()
{
    extern __shared__ float smem[];
    float*    Qs = smem;                         // [64][68] fp32
    float*    Ks = smem + 64 * 68;               // [64][68] fp32
    unsigned* Vs = (unsigned*)(smem + 2 * 64 * 68);  // [64][68] tf32 bits
    unsigned* Ps = (unsigned*)(smem + 3 * 64 * 68);  // [64][68] tf32 bits
    float* alpha_s = smem + 4 * 64 * 68;         // [64]
    float* l_s     = smem + 4 * 64 * 68 + 64;    // [64]

    const int bh = blockIdx.y;
    const int q0 = (gridDim.x - 1 - blockIdx.x) * 64;   // longest first
    const int b  = bh >> 4, h = bh & 15;
    const float* Qp = g_Q + (size_t)bh * S_LEN * HDIM;
    const float* Kp = g_K + (size_t)bh * S_LEN * HDIM;
    const float* Vp = g_V + (size_t)b * S_LEN * DMODEL + h * HDIM;

    const int tid  = threadIdx.x;
    const int lane = tid & 31;
    const int wid  = tid >> 5;
    const int ty = tid >> 4, tx = tid & 15;
    const int r0 = ty * 8, c0 = tx * 4;
    const unsigned FULL = 0xffffffffu;

    for (int it = tid; it < 64 * 16; it += 128) {
        int row = it >> 4, c4 = (it & 15) * 4;
        *(float4*)&Qs[row * 68 + c4] = *(const float4*)(Qp + (size_t)(q0 + row) * HDIM + c4);
    }

    float m[8], l[8];
    #pragma unroll
    for (int i = 0; i < 8; ++i) { m[i] = -1e30f; l[i] = 0.f; }

    float c[8][4];                       // PV accumulators (fragment layout)
    #pragma unroll
    for (int nf = 0; nf < 8; ++nf)
        #pragma unroll
        for (int e = 0; e < 4; ++e) c[nf][e] = 0.f;
    const int frow = wid * 16 + (lane >> 2);   // fragment row (0..63)

    const int ktmax = (q0 + 63) >> 6;
    for (int kt = 0; kt <= ktmax; ++kt) {
        __syncthreads();
        const int k0 = kt * 64;
        for (int it = tid; it < 1024; it += 128) {
            int row = it >> 4, c4 = (it & 15) * 4;
            *(float4*)&Ks[row * 68 + c4] = *(const float4*)(Kp + (size_t)(k0 + row) * HDIM + c4);
            float4 v = *(const float4*)(Vp + (size_t)(k0 + row) * DMODEL + c4);
            Vs[row * 68 + c4 + 0] = f2tf32(v.x);
            Vs[row * 68 + c4 + 1] = f2tf32(v.y);
            Vs[row * 68 + c4 + 2] = f2tf32(v.z);
            Vs[row * 68 + c4 + 3] = f2tf32(v.w);
        }
        __syncthreads();

        // QK^T: serial ascending-d fmaf chain (bitwise FROZEN)
        float s[8][4];
        #pragma unroll
        for (int i = 0; i < 8; ++i)
            #pragma unroll
            for (int j = 0; j < 4; ++j) s[i][j] = 0.f;

        #pragma unroll 4
        for (int d4 = 0; d4 < 16; ++d4) {
            float4 rk[4];
            #pragma unroll
            for (int j = 0; j < 4; ++j) rk[j] = *(float4*)&Ks[(c0 + j) * 68 + d4 * 4];
            #pragma unroll
            for (int i = 0; i < 8; ++i) {
                float4 rq = *(float4*)&Qs[(r0 + i) * 68 + d4 * 4];
                #pragma unroll
                for (int j = 0; j < 4; ++j) {
                    s[i][j] = fmaf(rq.x, rk[j].x, s[i][j]);
                    s[i][j] = fmaf(rq.y, rk[j].y, s[i][j]);
                    s[i][j] = fmaf(rq.z, rk[j].z, s[i][j]);
                    s[i][j] = fmaf(rq.w, rk[j].w, s[i][j]);
                }
            }
        }

        // scale (exact /8) + causal mask (FROZEN)
        #pragma unroll
        for (int i = 0; i < 8; ++i) {
            int qi = q0 + r0 + i;
            #pragma unroll
            for (int j = 0; j < 4; ++j) {
                int kj = k0 + c0 + j;
                s[i][j] = (kj <= qi) ? s[i][j] * 0.125f : -1e10f;
            }
        }

        // per-row online softmax + tile-max recording (FROZEN reductions)
        #pragma unroll
        for (int i = 0; i < 8; ++i) {
            float tmax = fmaxf(fmaxf(s[i][0], s[i][1]), fmaxf(s[i][2], s[i][3]));
            tmax = fmaxf(tmax, __shfl_xor_sync(FULL, tmax, 1));
            tmax = fmaxf(tmax, __shfl_xor_sync(FULL, tmax, 2));
            if ((tx & 3) == 0) {
                int tile = kt * 4 + (tx >> 2);
                int qi = q0 + r0 + i;
                g_TM[((size_t)bh * S_LEN + qi) * NTILES + tile] = tmax;
            }
            float rmax = fmaxf(tmax, __shfl_xor_sync(FULL, tmax, 4));
            rmax = fmaxf(rmax, __shfl_xor_sync(FULL, rmax, 8));

            float mnew  = fmaxf(m[i], rmax);
            float alpha = __expf(m[i] - mnew);
            m[i] = mnew;

            float psum = 0.f;
            #pragma unroll
            for (int j = 0; j < 4; ++j) {
                float p = __expf(s[i][j] - mnew);
                s[i][j] = p;
                psum += p;
            }
            psum += __shfl_xor_sync(FULL, psum, 1);
            psum += __shfl_xor_sync(FULL, psum, 2);
            psum += __shfl_xor_sync(FULL, psum, 4);
            psum += __shfl_xor_sync(FULL, psum, 8);
            l[i] = l[i] * alpha + psum;

            if (tx == 0) alpha_s[r0 + i] = alpha;
            #pragma unroll
            for (int j = 0; j < 4; ++j)
                Ps[(r0 + i) * 68 + c0 + j] = f2tf32(s[i][j]);
        }
        __syncthreads();

        // PV via tf32 mma: O_frag = alpha * O_frag + P @ V
        float a_lo = alpha_s[frow];
        float a_hi = alpha_s[frow + 8];
        #pragma unroll
        for (int nf = 0; nf < 8; ++nf) {
            c[nf][0] *= a_lo; c[nf][1] *= a_lo;
            c[nf][2] *= a_hi; c[nf][3] *= a_hi;
        }
        #pragma unroll
        for (int kb = 0; kb < 8; ++kb) {
            int klo = kb * 8 + (lane & 3);
            int khi = klo + 4;
            unsigned a0 = Ps[frow * 68 + klo];
            unsigned a1 = Ps[(frow + 8) * 68 + klo];
            unsigned a2 = Ps[frow * 68 + khi];
            unsigned a3 = Ps[(frow + 8) * 68 + khi];
            #pragma unroll
            for (int nf = 0; nf < 8; ++nf) {
                unsigned b0 = Vs[klo * 68 + nf * 8 + (lane >> 2)];
                unsigned b1 = Vs[khi * 68 + nf * 8 + (lane >> 2)];
                MMA_TF32(c[nf], a0, a1, a2, a3, b0, b1);
            }
        }
    }

    // publish l to smem, then fragment-layout epilogue
    if (tx == 0) {
        #pragma unroll
        for (int i = 0; i < 8; ++i) l_s[r0 + i] = l[i];
    }
    __syncthreads();

    {
        float inv_lo = 1.0f / l_s[frow];
        float inv_hi = 1.0f / l_s[frow + 8];
        int q_lo = q0 + frow, q_hi = q0 + frow + 8;
        float* op_lo = g_O + ((size_t)b * S_LEN + q_lo) * DMODEL + h * HDIM;
        float* op_hi = g_O + ((size_t)b * S_LEN + q_hi) * DMODEL + h * HDIM;
        #pragma unroll
        for (int nf = 0; nf < 8; ++nf) {
            int d = nf * 8 + (lane & 3) * 2;
            *(float2*)(op_lo + d) = make_float2(c[nf][0] * inv_lo, c[nf][1] * inv_lo);
            *(float2*)(op_hi + d) = make_float2(c[nf][2] * inv_hi, c[nf][3] * inv_hi);
        }
    }
}

// ---------------- top-8 tile selection by logit (one warp per query row) -----
__global__ void topk_kernel(float* __restrict__ oidx)
{
    int gw   = (blockIdx.x * blockDim.x + threadIdx.x) >> 5;
    int lane = threadIdx.x & 31;
    int q = gw & (S_LEN - 1);
    int qtile = q >> 4;
    const float* tm = g_TM + (size_t)gw * NTILES;

    float v[4];
    #pragma unroll
    for (int u = 0; u < 4; ++u) {
        int t = lane + u * 32;
        v[u] = (t <= qtile) ? tm[t] : -1e10f;
    }

    float* o = oidx + (size_t)gw * 8;
    for (int sel = 0; sel < 8; ++sel) {
        float bv = v[0]; int bi = lane;
        #pragma unroll
        for (int u = 1; u < 4; ++u) {
            int t = lane + u * 32;
            if (v[u] > bv) { bv = v[u]; bi = t; }
        }
        #pragma unroll
        for (int off = 16; off > 0; off >>= 1) {
            float ov = __shfl_xor_sync(0xffffffffu, bv, off);
            int   oi = __shfl_xor_sync(0xffffffffu, bi, off);
            if (ov > bv || (ov == bv && oi < bi)) { bv = ov; bi = oi; }
        }
        if (lane == 0) o[sel] = (float)bi;
        if ((bi & 31) == lane) v[bi >> 5] = -3.0e38f;
    }
}

// ---------------- launch ------------------------------------------------------
extern "C" void kernel_launch(void* const* d_in, const int* in_sizes, int n_in,
                              void* d_out, int out_size)
{
    const float*  x  = (const float*)d_in[0];
    const float*  wq = (const float*)d_in[1];
    const float*  wk = (const float*)d_in[2];
    const float*  wv = (const float*)d_in[3];
    const float*  wo = (const float*)d_in[4];
    float* out = (float*)d_out;

    float *qb, *kb, *vb, *ob;
    cudaGetSymbolAddress((void**)&qb,  g_Q);
    cudaGetSymbolAddress((void**)&kb,  g_K);
    cudaGetSymbolAddress((void**)&vb,  g_V);
    cudaGetSymbolAddress((void**)&ob,  g_O);

    fc_kernel<<<(FCN + 255) / 256, 256>>>();

    // Q & K projections in one launch (grid.z selects weight/output)
    int qk_smem = (4096 + 256 * 64) * (int)sizeof(float);   // 81920 B
    cudaFuncSetAttribute(sgemm_qk_panel, cudaFuncAttributeMaxDynamicSharedMemorySize, qk_smem);
    dim3 qk_grid(DMODEL / 128, NROWS / 128, 2);
    sgemm_qk_panel<<<qk_grid, 256, qk_smem>>>(x, wq, wk, qb, kb, DMODEL, DMODEL);

    // V projection: tf32 tensor cores (out0-only)
    dim3 gemm_grid(DMODEL / 128, NROWS / 128);
    sgemm_tf32<<<gemm_grid, 256>>>(x, wv, vb, DMODEL, DMODEL);

    rope_kernel<<<(1 << 22) / 256, 256>>>();

    int smem_bytes = (4 * 64 * 68 + 128) * (int)sizeof(float);  // 70144 B
    cudaFuncSetAttribute(attn_kernel, cudaFuncAttributeMaxDynamicSharedMemorySize, smem_bytes);
    attn_kernel<<<dim3(S_LEN / 64, BATCH * NHEAD), 128, smem_bytes>>>();

    // O projection: tf32 tensor cores (out0-only)
    sgemm_tf32<<<gemm_grid, 256>>>(ob, wo, out, DMODEL, DMODEL);

    if ((size_t)out_size >= OUT_ELEMS + IDX_ELEMS) {
        topk_kernel<<<(BATCH * NHEAD * S_LEN * 32) / 256, 256>>>(out + OUT_ELEMS);
    }
}